// round 1
// baseline (speedup 1.0000x reference)
#include <cuda_runtime.h>
#include <cuda_bf16.h>
#include <cstdint>

#define N_DE 12288
#define M_X  2048
#define DIM  128
#define TILE 128
#define T_BLOCKS (N_DE / TILE)                      // 96
#define KXX_BLOCKS (T_BLOCKS * (T_BLOCKS + 1) / 2)  // 4656
#define M_TILES (M_X / TILE)                        // 16
#define SMEM_BYTES (2 * TILE * DIM * 2 + 3 * TILE * 4)  // 67072

// -0.5/512 * log2(e), -0.5/10 * log2(e)
__device__ const float C1 = -0.0014088819735243784f;
__device__ const float C2 = -0.07213475204444817f;

__device__ __align__(16) __nv_bfloat16 g_De_bf[N_DE * DIM];
__device__ __align__(16) __nv_bfloat16 g_X_bf[M_X * DIM];
__device__ float  g_sq_de[N_DE];
__device__ float  g_sq_x[M_X];
__device__ double g_kxx;
__device__ float  g_kxy[M_X];

__device__ __forceinline__ float ex2f(float x) {
    float y;
    asm("ex2.approx.ftz.f32 %0, %1;" : "=f"(y) : "f"(x));
    return y;
}

// ---------------- prep: fp32 -> bf16 + row squared norms + zero accumulators --------
__global__ void prep_kernel(const float* __restrict__ De, const float* __restrict__ X) {
    if (blockIdx.x == 0) {
        for (int i = threadIdx.x; i < M_X; i += blockDim.x) g_kxy[i] = 0.f;
        if (threadIdx.x == 0) g_kxx = 0.0;
    }
    int warp = (blockIdx.x * blockDim.x + threadIdx.x) >> 5;
    int lane = threadIdx.x & 31;
    if (warp >= N_DE + M_X) return;

    const float* src;
    __nv_bfloat16* dst;
    float* sq;
    if (warp < N_DE) {
        src = De + (size_t)warp * DIM;
        dst = g_De_bf + (size_t)warp * DIM;
        sq  = g_sq_de + warp;
    } else {
        int r = warp - N_DE;
        src = X + (size_t)r * DIM;
        dst = g_X_bf + (size_t)r * DIM;
        sq  = g_sq_x + r;
    }
    float4 v = ((const float4*)src)[lane];
    float s = v.x * v.x + v.y * v.y + v.z * v.z + v.w * v.w;
    __nv_bfloat162 p0 = __float22bfloat162_rn(make_float2(v.x, v.y));
    __nv_bfloat162 p1 = __float22bfloat162_rn(make_float2(v.z, v.w));
    uint2 u;
    u.x = *(unsigned*)&p0;
    u.y = *(unsigned*)&p1;
    ((uint2*)dst)[lane] = u;
#pragma unroll
    for (int o = 16; o; o >>= 1) s += __shfl_xor_sync(0xffffffffu, s, o);
    if (lane == 0) *sq = s;
}

// ---------------- shared helpers ----------------------------------------------------
// byte address of bf16 element (r, c) in a 128x128 tile, 16B-chunk XOR swizzle
__device__ __forceinline__ unsigned sw_addr(unsigned sbase, int r, int c) {
    int chunk = (c >> 3) ^ (r & 7);
    return sbase + (unsigned)((r << 8) + (chunk << 4) + ((c & 7) << 1));
}

__device__ __forceinline__ void ldm4(unsigned addr, unsigned& r0, unsigned& r1,
                                     unsigned& r2, unsigned& r3) {
    asm volatile("ldmatrix.sync.aligned.m8n8.x4.shared.b16 {%0,%1,%2,%3}, [%4];"
                 : "=r"(r0), "=r"(r1), "=r"(r2), "=r"(r3)
                 : "r"(addr));
}

__device__ __forceinline__ void mma16816(float* c, unsigned a0, unsigned a1, unsigned a2,
                                         unsigned a3, unsigned b0, unsigned b1) {
    asm volatile(
        "mma.sync.aligned.m16n8k16.row.col.f32.bf16.bf16.f32 "
        "{%0,%1,%2,%3},{%4,%5,%6,%7},{%8,%9},{%0,%1,%2,%3};"
        : "+f"(c[0]), "+f"(c[1]), "+f"(c[2]), "+f"(c[3])
        : "r"(a0), "r"(a1), "r"(a2), "r"(a3), "r"(b0), "r"(b1));
}

// 128x128 bf16 tile: global (row-major, 16 uint4/row) -> swizzled smem
__device__ __forceinline__ void load_tile(__nv_bfloat16* s, const __nv_bfloat16* g) {
    int t = threadIdx.x;
#pragma unroll
    for (int i = 0; i < 8; i++) {
        int id = t + i * 256;
        int r = id >> 4, c = id & 15;
        uint4 v = ((const uint4*)g)[(r << 4) + c];
        int pc = c ^ (r & 7);
        ((uint4*)s)[(r << 4) + pc] = v;
    }
}

// full-K (128) warp GEMM: 64x32 output per warp, acc[mi][ni][4]
__device__ __forceinline__ void gemm_tile(unsigned sA, unsigned sB, int wm, int wn, int lane,
                                          float (&acc)[4][4][4]) {
    int lrA = lane & 15, lcA = (lane >> 4) << 3;
    int grp = lane >> 3, w8 = lane & 7;
    int rB = ((grp & 2) << 2) + w8;
    int cB = (grp & 1) << 3;
#pragma unroll
    for (int kk = 0; kk < 8; kk++) {
        int k0 = kk << 4;
        unsigned a[4][4];
#pragma unroll
        for (int mi = 0; mi < 4; mi++)
            ldm4(sw_addr(sA, wm + mi * 16 + lrA, k0 + lcA),
                 a[mi][0], a[mi][1], a[mi][2], a[mi][3]);
        unsigned b[4][2];
        {
            unsigned r0, r1, r2, r3;
            ldm4(sw_addr(sB, wn + rB, k0 + cB), r0, r1, r2, r3);
            b[0][0] = r0; b[0][1] = r1; b[1][0] = r2; b[1][1] = r3;
            ldm4(sw_addr(sB, wn + 16 + rB, k0 + cB), r0, r1, r2, r3);
            b[2][0] = r0; b[2][1] = r1; b[3][0] = r2; b[3][1] = r3;
        }
#pragma unroll
        for (int mi = 0; mi < 4; mi++)
#pragma unroll
            for (int ni = 0; ni < 4; ni++)
                mma16816(acc[mi][ni], a[mi][0], a[mi][1], a[mi][2], a[mi][3],
                         b[ni][0], b[ni][1]);
    }
}

// ---------------- kxx: upper-triangular tiles of De x De ----------------------------
__global__ void __launch_bounds__(256, 2) kxx_kernel() {
    extern __shared__ char smem_raw[];
    __nv_bfloat16* As = (__nv_bfloat16*)smem_raw;
    __nv_bfloat16* Bs = As + TILE * DIM;
    float* sqa = (float*)(Bs + TILE * DIM);
    float* sqb = sqa + TILE;
    __shared__ float s_bsum;

    int t = threadIdx.x;
    int lane = t & 31, warp = t >> 5;

    // linear block id -> (bi, bj), bi <= bj
    int tb = blockIdx.x;
    const int Tn = T_BLOCKS;
    int bi = (int)((2 * Tn + 1 - sqrtf((float)((2 * Tn + 1) * (2 * Tn + 1) - 8 * tb))) * 0.5f);
    while (bi * Tn - bi * (bi - 1) / 2 > tb) bi--;
    while ((bi + 1) * Tn - (bi + 1) * bi / 2 <= tb) bi++;
    int bj = bi + (tb - (bi * Tn - bi * (bi - 1) / 2));

    if (t == 0) s_bsum = 0.f;
    load_tile(As, g_De_bf + (size_t)bi * TILE * DIM);
    load_tile(Bs, g_De_bf + (size_t)bj * TILE * DIM);
    if (t < 128) sqa[t] = g_sq_de[bi * TILE + t];
    else         sqb[t - 128] = g_sq_de[bj * TILE + (t - 128)];
    __syncthreads();

    int wm = (warp >> 2) * 64;
    int wn = (warp & 3) * 32;
    float acc[4][4][4];
#pragma unroll
    for (int i = 0; i < 4; i++)
#pragma unroll
        for (int j = 0; j < 4; j++)
#pragma unroll
            for (int e = 0; e < 4; e++) acc[i][j][e] = 0.f;

    unsigned sA = (unsigned)__cvta_generic_to_shared(As);
    unsigned sB = (unsigned)__cvta_generic_to_shared(Bs);
    gemm_tile(sA, sB, wm, wn, lane, acc);

    float s = 0.f;
    int r0 = wm + (lane >> 2);
    int c0 = wn + ((lane & 3) << 1);
#pragma unroll
    for (int mi = 0; mi < 4; mi++) {
        float sr0 = sqa[r0 + mi * 16];
        float sr1 = sqa[r0 + mi * 16 + 8];
#pragma unroll
        for (int ni = 0; ni < 4; ni++) {
            float sc0 = sqb[c0 + ni * 8];
            float sc1 = sqb[c0 + ni * 8 + 1];
            float d2;
            d2 = fmaf(-2.f, acc[mi][ni][0], sr0 + sc0); s += ex2f(C1 * d2) + ex2f(C2 * d2);
            d2 = fmaf(-2.f, acc[mi][ni][1], sr0 + sc1); s += ex2f(C1 * d2) + ex2f(C2 * d2);
            d2 = fmaf(-2.f, acc[mi][ni][2], sr1 + sc0); s += ex2f(C1 * d2) + ex2f(C2 * d2);
            d2 = fmaf(-2.f, acc[mi][ni][3], sr1 + sc1); s += ex2f(C1 * d2) + ex2f(C2 * d2);
        }
    }
#pragma unroll
    for (int o = 16; o; o >>= 1) s += __shfl_xor_sync(0xffffffffu, s, o);
    if (lane == 0) atomicAdd(&s_bsum, s);
    __syncthreads();
    if (t == 0) {
        double w = (bi == bj) ? 1.0 : 2.0;
        atomicAdd(&g_kxx, w * (double)s_bsum);
    }
}

// ---------------- kxy: X x De, per-row sums ------------------------------------------
__global__ void __launch_bounds__(256, 2) kxy_kernel() {
    extern __shared__ char smem_raw[];
    __nv_bfloat16* As = (__nv_bfloat16*)smem_raw;
    __nv_bfloat16* Bs = As + TILE * DIM;
    float* sqa = (float*)(Bs + TILE * DIM);
    float* sqb = sqa + TILE;
    float* srow = sqb + TILE;

    int t = threadIdx.x;
    int lane = t & 31, warp = t >> 5;
    int bn = blockIdx.x, bm = blockIdx.y;

    load_tile(As, g_X_bf + (size_t)bm * TILE * DIM);
    load_tile(Bs, g_De_bf + (size_t)bn * TILE * DIM);
    if (t < 128) { sqa[t] = g_sq_x[bm * TILE + t]; srow[t] = 0.f; }
    else         { sqb[t - 128] = g_sq_de[bn * TILE + (t - 128)]; }
    __syncthreads();

    int wm = (warp >> 2) * 64;
    int wn = (warp & 3) * 32;
    float acc[4][4][4];
#pragma unroll
    for (int i = 0; i < 4; i++)
#pragma unroll
        for (int j = 0; j < 4; j++)
#pragma unroll
            for (int e = 0; e < 4; e++) acc[i][j][e] = 0.f;

    unsigned sA = (unsigned)__cvta_generic_to_shared(As);
    unsigned sB = (unsigned)__cvta_generic_to_shared(Bs);
    gemm_tile(sA, sB, wm, wn, lane, acc);

    float p[4][2];
#pragma unroll
    for (int i = 0; i < 4; i++) { p[i][0] = 0.f; p[i][1] = 0.f; }

    int r0 = wm + (lane >> 2);
    int c0 = wn + ((lane & 3) << 1);
#pragma unroll
    for (int mi = 0; mi < 4; mi++) {
        float sr0 = sqa[r0 + mi * 16];
        float sr1 = sqa[r0 + mi * 16 + 8];
#pragma unroll
        for (int ni = 0; ni < 4; ni++) {
            float sc0 = sqb[c0 + ni * 8];
            float sc1 = sqb[c0 + ni * 8 + 1];
            float d2;
            d2 = fmaf(-2.f, acc[mi][ni][0], sr0 + sc0); p[mi][0] += ex2f(C1 * d2) + ex2f(C2 * d2);
            d2 = fmaf(-2.f, acc[mi][ni][1], sr0 + sc1); p[mi][0] += ex2f(C1 * d2) + ex2f(C2 * d2);
            d2 = fmaf(-2.f, acc[mi][ni][2], sr1 + sc0); p[mi][1] += ex2f(C1 * d2) + ex2f(C2 * d2);
            d2 = fmaf(-2.f, acc[mi][ni][3], sr1 + sc1); p[mi][1] += ex2f(C1 * d2) + ex2f(C2 * d2);
        }
    }
#pragma unroll
    for (int mi = 0; mi < 4; mi++)
#pragma unroll
        for (int h = 0; h < 2; h++) {
            float v = p[mi][h];
            v += __shfl_xor_sync(0xffffffffu, v, 1);
            v += __shfl_xor_sync(0xffffffffu, v, 2);
            if ((lane & 3) == 0) {
                int row = wm + mi * 16 + (lane >> 2) + h * 8;
                atomicAdd(&srow[row], v);
            }
        }
    __syncthreads();
    if (t < 128) atomicAdd(&g_kxy[bm * TILE + t], srow[t]);
}

// ---------------- finalize -----------------------------------------------------------
__global__ void final_kernel(float* __restrict__ out) {
    int m = blockIdx.x * blockDim.x + threadIdx.x;
    if (m < M_X) {
        float kxx_mean = (float)(g_kxx / ((double)N_DE * (double)N_DE));
        out[m] = kxx_mean + 2.0f - 2.0f * (g_kxy[m] * (1.0f / (float)N_DE));
    }
}

extern "C" void kernel_launch(void* const* d_in, const int* in_sizes, int n_in,
                              void* d_out, int out_size) {
    const float* De = (const float*)d_in[0];
    const float* X  = (const float*)d_in[1];
    float* out = (float*)d_out;

    cudaFuncSetAttribute(kxx_kernel, cudaFuncAttributeMaxDynamicSharedMemorySize, SMEM_BYTES);
    cudaFuncSetAttribute(kxy_kernel, cudaFuncAttributeMaxDynamicSharedMemorySize, SMEM_BYTES);

    prep_kernel<<<(N_DE + M_X) / 4, 128>>>(De, X);
    kxx_kernel<<<KXX_BLOCKS, 256, SMEM_BYTES>>>();
    kxy_kernel<<<dim3(T_BLOCKS, M_TILES), 256, SMEM_BYTES>>>();
    final_kernel<<<(M_X + 127) / 128, 128>>>(out);
}